// round 14
// baseline (speedup 1.0000x reference)
#include <cuda_runtime.h>
#include <cuda_bf16.h>
#include <math.h>

#define HIDDEN    128
#define STATE_DIM 6
#define NUM_STEPS 8
#define MAX_STD   2.0f
#define MIN_STD   0.1f

// Combined blocked table: row j (input unit j) = 256 floats (1024 B):
//   floats [0..127]   : fc2t  row j  (c12[j*256 + i]       = w_fc2 [i*128 + j])
//   floats [128..255] : rec1t row j  (c12[j*256 + 128 + i] = w_rec1[i*128 + j])
__device__ float g_c12  [HIDDEN * 256];
__device__ float g_rec2t[HIDDEN * HIDDEN];   // rec2t[j*128 + i] = w_rec2[i*128 + j]
__device__ float g_fc1t [STATE_DIM * HIDDEN];

typedef unsigned long long u64;

__device__ __forceinline__ u64 pack2(float lo, float hi) {
    u64 r; asm("mov.b64 %0, {%1, %2};" : "=l"(r) : "f"(lo), "f"(hi)); return r;
}
__device__ __forceinline__ void unpack2(u64 v, float& lo, float& hi) {
    asm("mov.b64 {%0, %1}, %2;" : "=f"(lo), "=f"(hi) : "l"(v));
}
__device__ __forceinline__ u64 add2(u64 a, u64 b) {
    u64 r; asm("add.rn.f32x2 %0, %1, %2;" : "=l"(r) : "l"(a), "l"(b)); return r;
}
__device__ __forceinline__ u64 mul2(u64 a, u64 b) {
    u64 r; asm("mul.rn.f32x2 %0, %1, %2;" : "=l"(r) : "l"(a), "l"(b)); return r;
}
__device__ __forceinline__ u64 fma2(u64 a, u64 b, u64 c) {
    u64 r; asm("fma.rn.f32x2 %0, %1, %2, %3;" : "=l"(r) : "l"(a), "l"(b), "l"(c)); return r;
}
__device__ __forceinline__ unsigned bfind(unsigned x) {
    unsigned r; asm("bfind.u32 %0, %1;" : "=r"(r) : "r"(x)); return r;
}

__global__ void snn_transpose_kernel(const float* __restrict__ w_fc1,
                                     const float* __restrict__ w_rec1,
                                     const float* __restrict__ w_fc2,
                                     const float* __restrict__ w_rec2) {
    int idx = blockIdx.x * blockDim.x + threadIdx.x;   // over 128*128
    if (idx < HIDDEN * HIDDEN) {
        int i = idx / HIDDEN;      // output unit
        int j = idx % HIDDEN;      // input unit (row of table)
        g_c12[j * 256 + i]       = w_fc2 [idx];
        g_c12[j * 256 + 128 + i] = w_rec1[idx];
        g_rec2t[j * HIDDEN + i]  = w_rec2[idx];
        if (idx < HIDDEN * STATE_DIM) {
            int ii = idx / STATE_DIM;
            int d  = idx % STATE_DIM;
            g_fc1t[d * HIDDEN + ii] = w_fc1[idx];
        }
    }
}

// Fused gather over layer-1 spike mask: set bit (w,l) -> unit j=4l+w.
// fc2 row -> s01/s23 (syn2, this step). If WITH_REC1, also rec1 row ->
// r01/r23 (next step's syn1) — skipped on the final step (value dead).
template <bool WITH_REC1>
__device__ __forceinline__ void gather_fused(const unsigned m[4], int lane,
                                             u64& s01, u64& s23,
                                             u64& r01, u64& r23) {
    const char* base = reinterpret_cast<const char*>(g_c12) + lane * 16;
#pragma unroll
    for (int w = 0; w < 4; w++) {
        unsigned mm = m[w];
        const char* bw = base + w * 1024;
        while (mm) {
            unsigned l = bfind(mm);
            mm -= (1u << l);
            const char* p = bw + l * 4096u;
            ulonglong2 vf = *reinterpret_cast<const ulonglong2*>(p);            // fc2
            s01 = add2(s01, vf.x);
            s23 = add2(s23, vf.y);
            if (WITH_REC1) {
                ulonglong2 vr = *reinterpret_cast<const ulonglong2*>(p + 512);  // rec1
                r01 = add2(r01, vr.x);
                r23 = add2(r23, vr.y);
            }
        }
    }
}

// Plain gather (rare layer-2 recurrent path).
__device__ __forceinline__ void gather2(const float* __restrict__ Wt,
                                        const unsigned* m, int lane,
                                        u64& a01, u64& a23) {
    const char* base = reinterpret_cast<const char*>(Wt) + lane * 16;
#pragma unroll
    for (int w = 0; w < 4; w++) {
        unsigned mm = m[w];
        const char* bw = base + w * 512;
        while (mm) {
            unsigned l = bfind(mm);
            mm -= (1u << l);
            ulonglong2 v = *reinterpret_cast<const ulonglong2*>(bw + l * 2048u);
            a01 = add2(a01, v.x);
            a23 = add2(a23, v.y);
        }
    }
}

__global__ void __launch_bounds__(128, 12)
snn_main_kernel(const float* __restrict__ state,
                const float* __restrict__ w_mean,
                const float* __restrict__ w_std,
                const float* __restrict__ p_a1, const float* __restrict__ p_b1,
                const float* __restrict__ p_t1, const float* __restrict__ p_a2,
                const float* __restrict__ p_b2, const float* __restrict__ p_t2,
                float* __restrict__ out, int B) {
    int gtid = blockIdx.x * blockDim.x + threadIdx.x;
    int b    = gtid >> 5;          // one warp per batch element
    int lane = threadIdx.x & 31;
    if (b >= B) return;

    const float a1 = fminf(fmaxf(*p_a1, 0.f), 1.f);
    const float b1 = fminf(fmaxf(*p_b1, 0.f), 1.f);
    const float a2 = fminf(fmaxf(*p_a2, 0.f), 1.f);
    const float b2 = fminf(fmaxf(*p_b2, 0.f), 1.f);
    const float thr1 = *p_t1;
    const float thr2 = *p_t2;
    const float nthr1 = -thr1;     // spike value for reset-by-subtract

    const u64 a1p = pack2(a1, a1), b1p = pack2(b1, b1);

    // cur1_in = state[b] @ w_fc1.T (constant across steps), packed.
    u64 cur01 = 0, cur23 = 0;
    {
        const float2* srow = reinterpret_cast<const float2*>(state + (long)b * STATE_DIM);
#pragma unroll
        for (int dp = 0; dp < 3; dp++) {
            float2 sd2 = __ldg(srow + dp);
#pragma unroll
            for (int e = 0; e < 2; e++) {
                int d = 2 * dp + e;
                float sd = e ? sd2.y : sd2.x;
                u64 sdp = pack2(sd, sd);
                ulonglong2 w = *reinterpret_cast<const ulonglong2*>(g_fc1t + d * HIDDEN + 4 * lane);
                cur01 = fma2(sdp, w.x, cur01);
                cur23 = fma2(sdp, w.y, cur23);
            }
        }
    }

    u64 syn1_01 = 0, syn1_23 = 0, mem1_01 = 0, mem1_23 = 0;
    u64 syn2_01 = 0, syn2_23 = 0, mem2_01 = 0, mem2_23 = 0;
    u64 spk1n_01 = 0, spk1n_23 = 0;   // spike "values" {0,-thr1}
    u64 r1p01 = 0, r1p23 = 0;         // pending rec1 contribution
    // cnt32: byte k = spike count for unit k (bits 0..6) | "spiked last step"
    // flag (bit 7). Counts <= 8 so no overflow into the flag.
    unsigned cnt32 = 0;
    bool live1 = !(thr2 > 0.f);       // force full path if thr2 <= 0 / NaN
    bool live2 = false;               // layer-2 spiked on previous step

#pragma unroll
    for (int t = 0; t < NUM_STEPS; t++) {
        const bool LAST = (t == NUM_STEPS - 1);

        // ---------- layer 1 state ----------
        syn1_01 = fma2(a1p, syn1_01, cur01);
        syn1_23 = fma2(a1p, syn1_23, cur23);
        if (live1) {
            syn1_01 = add2(syn1_01, r1p01);
            syn1_23 = add2(syn1_23, r1p23);
            mem1_01 = fma2(b1p, mem1_01, syn1_01);
            mem1_23 = fma2(b1p, mem1_23, syn1_23);
            mem1_01 = add2(mem1_01, spk1n_01);   // reset-by-subtract ({0,-thr1})
            mem1_23 = add2(mem1_23, spk1n_23);
        } else {
            mem1_01 = fma2(b1p, mem1_01, syn1_01);
            mem1_23 = fma2(b1p, mem1_23, syn1_23);
        }

        float f0, f1, f2, f3;
        unpack2(mem1_01, f0, f1);
        unpack2(mem1_23, f2, f3);
        bool s0 = f0 > thr1, s1 = f1 > thr1, s2 = f2 > thr1, s3 = f3 > thr1;

        bool active;
        if (live1) active = true;
        else       active = __any_sync(0xffffffffu, s0 | s1 | s2 | s3);

        if (active) {
            live1 = true;
            unsigned m1[4];
            m1[0] = __ballot_sync(0xffffffffu, s0);
            m1[1] = __ballot_sync(0xffffffffu, s1);
            m1[2] = __ballot_sync(0xffffffffu, s2);
            m1[3] = __ballot_sync(0xffffffffu, s3);
            if (!LAST) {
                spk1n_01 = pack2(s0 ? nthr1 : 0.f, s1 ? nthr1 : 0.f);
                spk1n_23 = pack2(s2 ? nthr1 : 0.f, s3 ? nthr1 : 0.f);
            }

            // ---------- layer 2 (+ pre-gather next step's rec1 if needed) ----------
            u64 a2p = pack2(a2, a2);
            syn2_01 = mul2(a2p, syn2_01);
            syn2_23 = mul2(a2p, syn2_23);
            if (!LAST) {
                r1p01 = 0; r1p23 = 0;
                gather_fused<true>(m1, lane, syn2_01, syn2_23, r1p01, r1p23);
            } else {
                gather_fused<false>(m1, lane, syn2_01, syn2_23, r1p01, r1p23);
            }
            if (live2) {
                // re-ballot the previous step's layer-2 spike mask from the
                // per-thread flag bits stashed in cnt32 (rare path)
                unsigned m2w[4];
                m2w[0] = __ballot_sync(0xffffffffu, (cnt32 >> 7)  & 1u);
                m2w[1] = __ballot_sync(0xffffffffu, (cnt32 >> 15) & 1u);
                m2w[2] = __ballot_sync(0xffffffffu, (cnt32 >> 23) & 1u);
                m2w[3] = __ballot_sync(0xffffffffu, (cnt32 >> 31) & 1u);
                gather2(g_rec2t, m2w, lane, syn2_01, syn2_23);
            }

            u64 b2p = pack2(b2, b2);
            mem2_01 = fma2(b2p, mem2_01, syn2_01);
            mem2_23 = fma2(b2p, mem2_23, syn2_23);
            if (live2) {
                // reset values {0,-thr2} from this thread's own flag bits (rare)
                float nthr2 = -thr2;
                float r0 = ((cnt32 >> 7)  & 1u) ? nthr2 : 0.f;
                float r1 = ((cnt32 >> 15) & 1u) ? nthr2 : 0.f;
                float r2 = ((cnt32 >> 23) & 1u) ? nthr2 : 0.f;
                float r3 = ((cnt32 >> 31) & 1u) ? nthr2 : 0.f;
                mem2_01 = add2(mem2_01, pack2(r0, r1));
                mem2_23 = add2(mem2_23, pack2(r2, r3));
            }

            unpack2(mem2_01, f0, f1);
            unpack2(mem2_23, f2, f3);
            bool t0 = f0 > thr2, t1 = f1 > thr2, t2 = f2 > thr2, t3 = f3 > thr2;
            if (__any_sync(0xffffffffu, t0 | t1 | t2 | t3)) {
                unsigned counts = (t0 ? 1u : 0u) | (t1 ? (1u << 8) : 0u)
                                | (t2 ? (1u << 16) : 0u) | (t3 ? (1u << 24) : 0u);
                if (!LAST) {
                    unsigned flags = (t0 ? (1u << 7) : 0u)  | (t1 ? (1u << 15) : 0u)
                                   | (t2 ? (1u << 23) : 0u) | (t3 ? (1u << 31) : 0u);
                    cnt32 = ((cnt32 & 0x7F7F7F7Fu) + counts) | flags;
                    live2 = true;
                } else {
                    cnt32 = (cnt32 & 0x7F7F7F7Fu) + counts;   // flags dead after last step
                }
            } else if (!LAST && live2) {
                cnt32 &= 0x7F7F7F7Fu;   // clear stale flags
                live2 = false;
            }
        }
        // quiet step: spk1n/r1p/syn2/mem2/cnt32 all remain exactly 0.
    }

    // ---- epilogue ----
    // Common case: no layer-2 spike anywhere in this warp -> avg_spikes == 0
    // exactly -> dm = ds = 0 exactly (finite weights) -> constant outputs,
    // computed with the SAME float expressions as the slow path (bit-identical).
    if (!__any_sync(0xffffffffu, cnt32 != 0u)) {
        if (lane == 0) {
            out[b] = 0.0f;                              // tanhf(0) == 0
            float sig = 1.f / (1.f + expf(-2.f));       // sigmoid(0 + 2)
            out[B + b] = (MAX_STD - MIN_STD) * sig + MIN_STD;
        }
        return;
    }

    const float inv = 1.f / (float)NUM_STEPS;
    float c0 = (float)( cnt32        & 0x7Fu) * inv;
    float c1 = (float)((cnt32 >> 8)  & 0x7Fu) * inv;
    float c2 = (float)((cnt32 >> 16) & 0x7Fu) * inv;
    float c3 = (float)((cnt32 >> 24) & 0x7Fu) * inv;

    float4 wm = *reinterpret_cast<const float4*>(w_mean + 4 * lane);
    float4 ws = *reinterpret_cast<const float4*>(w_std  + 4 * lane);
    float dm = fmaf(c0, wm.x, fmaf(c1, wm.y, fmaf(c2, wm.z, c3 * wm.w)));
    float ds = fmaf(c0, ws.x, fmaf(c1, ws.y, fmaf(c2, ws.z, c3 * ws.w)));
#pragma unroll
    for (int off = 16; off > 0; off >>= 1) {
        dm += __shfl_xor_sync(0xffffffffu, dm, off);
        ds += __shfl_xor_sync(0xffffffffu, ds, off);
    }
    if (lane == 0) {
        out[b] = tanhf(dm);
        float sig = 1.f / (1.f + expf(-(ds + 2.f)));
        out[B + b] = (MAX_STD - MIN_STD) * sig + MIN_STD;
    }
}

extern "C" void kernel_launch(void* const* d_in, const int* in_sizes, int n_in,
                              void* d_out, int out_size) {
    const float* state  = (const float*)d_in[0];
    const float* w_fc1  = (const float*)d_in[1];
    const float* w_rec1 = (const float*)d_in[2];
    const float* w_fc2  = (const float*)d_in[3];
    const float* w_rec2 = (const float*)d_in[4];
    const float* w_mean = (const float*)d_in[5];
    const float* w_std  = (const float*)d_in[6];
    const float* a1 = (const float*)d_in[7];
    const float* b1 = (const float*)d_in[8];
    const float* t1 = (const float*)d_in[9];
    const float* a2 = (const float*)d_in[10];
    const float* b2 = (const float*)d_in[11];
    const float* t2 = (const float*)d_in[12];
    float* out = (float*)d_out;

    int B = in_sizes[0] / STATE_DIM;

    snn_transpose_kernel<<<128, 128>>>(w_fc1, w_rec1, w_fc2, w_rec2);

    int total_threads = B * 32;                    // one warp per element
    int blocks = (total_threads + 127) / 128;
    snn_main_kernel<<<blocks, 128>>>(state, w_mean, w_std,
                                     a1, b1, t1, a2, b2, t2, out, B);
}

// round 15
// speedup vs baseline: 1.0094x; 1.0094x over previous
#include <cuda_runtime.h>
#include <cuda_bf16.h>
#include <math.h>

#define HIDDEN    128
#define STATE_DIM 6
#define NUM_STEPS 8
#define MAX_STD   2.0f
#define MIN_STD   0.1f

// Combined blocked table: row j (input unit j) = 256 floats (1024 B):
//   floats [0..127]   : fc2t  row j  (c12[j*256 + i]       = w_fc2 [i*128 + j])
//   floats [128..255] : rec1t row j  (c12[j*256 + 128 + i] = w_rec1[i*128 + j])
__device__ float g_c12  [HIDDEN * 256];
__device__ float g_rec2t[HIDDEN * HIDDEN];   // rec2t[j*128 + i] = w_rec2[i*128 + j]
__device__ float g_fc1t [STATE_DIM * HIDDEN];

typedef unsigned long long u64;

__device__ __forceinline__ u64 pack2(float lo, float hi) {
    u64 r; asm("mov.b64 %0, {%1, %2};" : "=l"(r) : "f"(lo), "f"(hi)); return r;
}
__device__ __forceinline__ void unpack2(u64 v, float& lo, float& hi) {
    asm("mov.b64 {%0, %1}, %2;" : "=f"(lo), "=f"(hi) : "l"(v));
}
__device__ __forceinline__ u64 add2(u64 a, u64 b) {
    u64 r; asm("add.rn.f32x2 %0, %1, %2;" : "=l"(r) : "l"(a), "l"(b)); return r;
}
__device__ __forceinline__ u64 mul2(u64 a, u64 b) {
    u64 r; asm("mul.rn.f32x2 %0, %1, %2;" : "=l"(r) : "l"(a), "l"(b)); return r;
}
__device__ __forceinline__ u64 fma2(u64 a, u64 b, u64 c) {
    u64 r; asm("fma.rn.f32x2 %0, %1, %2, %3;" : "=l"(r) : "l"(a), "l"(b), "l"(c)); return r;
}
__device__ __forceinline__ unsigned bfind(unsigned x) {
    unsigned r; asm("bfind.u32 %0, %1;" : "=r"(r) : "r"(x)); return r;
}

__global__ void snn_transpose_kernel(const float* __restrict__ w_fc1,
                                     const float* __restrict__ w_rec1,
                                     const float* __restrict__ w_fc2,
                                     const float* __restrict__ w_rec2) {
    int idx = blockIdx.x * blockDim.x + threadIdx.x;   // over 128*128
    if (idx < HIDDEN * HIDDEN) {
        int i = idx / HIDDEN;      // output unit
        int j = idx % HIDDEN;      // input unit (row of table)
        g_c12[j * 256 + i]       = w_fc2 [idx];
        g_c12[j * 256 + 128 + i] = w_rec1[idx];
        g_rec2t[j * HIDDEN + i]  = w_rec2[idx];
        if (idx < HIDDEN * STATE_DIM) {
            int ii = idx / STATE_DIM;
            int d  = idx % STATE_DIM;
            g_fc1t[d * HIDDEN + ii] = w_fc1[idx];
        }
    }
}

// Fused gather over layer-1 spike mask: set bit (w,l) -> unit j=4l+w.
// fc2 row -> s01/s23 (syn2, this step). If WITH_REC1, also rec1 row ->
// r01/r23 (next step's syn1) — skipped on the final step (value dead).
template <bool WITH_REC1>
__device__ __forceinline__ void gather_fused(const unsigned m[4], int lane,
                                             u64& s01, u64& s23,
                                             u64& r01, u64& r23) {
    const char* base = reinterpret_cast<const char*>(g_c12) + lane * 16;
#pragma unroll
    for (int w = 0; w < 4; w++) {
        unsigned mm = m[w];
        const char* bw = base + w * 1024;
        while (mm) {
            unsigned l = bfind(mm);
            mm -= (1u << l);
            const char* p = bw + l * 4096u;
            ulonglong2 vf = *reinterpret_cast<const ulonglong2*>(p);            // fc2
            s01 = add2(s01, vf.x);
            s23 = add2(s23, vf.y);
            if (WITH_REC1) {
                ulonglong2 vr = *reinterpret_cast<const ulonglong2*>(p + 512);  // rec1
                r01 = add2(r01, vr.x);
                r23 = add2(r23, vr.y);
            }
        }
    }
}

// Plain gather (rare layer-2 recurrent path).
__device__ __forceinline__ void gather2(const float* __restrict__ Wt,
                                        const unsigned* m, int lane,
                                        u64& a01, u64& a23) {
    const char* base = reinterpret_cast<const char*>(Wt) + lane * 16;
#pragma unroll
    for (int w = 0; w < 4; w++) {
        unsigned mm = m[w];
        const char* bw = base + w * 512;
        while (mm) {
            unsigned l = bfind(mm);
            mm -= (1u << l);
            ulonglong2 v = *reinterpret_cast<const ulonglong2*>(bw + l * 2048u);
            a01 = add2(a01, v.x);
            a23 = add2(a23, v.y);
        }
    }
}

__global__ void __launch_bounds__(128, 10)
snn_main_kernel(const float* __restrict__ state,
                const float* __restrict__ w_mean,
                const float* __restrict__ w_std,
                const float* __restrict__ p_a1, const float* __restrict__ p_b1,
                const float* __restrict__ p_t1, const float* __restrict__ p_a2,
                const float* __restrict__ p_b2, const float* __restrict__ p_t2,
                float* __restrict__ out, int B) {
    int gtid = blockIdx.x * blockDim.x + threadIdx.x;
    int b    = gtid >> 5;          // one warp per batch element
    int lane = threadIdx.x & 31;
    if (b >= B) return;

    const float a1 = fminf(fmaxf(*p_a1, 0.f), 1.f);
    const float b1 = fminf(fmaxf(*p_b1, 0.f), 1.f);
    const float a2 = fminf(fmaxf(*p_a2, 0.f), 1.f);
    const float b2 = fminf(fmaxf(*p_b2, 0.f), 1.f);
    const float thr1 = *p_t1;
    const float thr2 = *p_t2;
    const float nthr1 = -thr1;     // spike value for reset-by-subtract

    const u64 a1p = pack2(a1, a1), b1p = pack2(b1, b1);
    const u64 a2p = pack2(a2, a2), b2p = pack2(b2, b2);

    // cur1_in = state[b] @ w_fc1.T (constant across steps), packed.
    u64 cur01 = 0, cur23 = 0;
    {
        const float2* srow = reinterpret_cast<const float2*>(state + (long)b * STATE_DIM);
#pragma unroll
        for (int dp = 0; dp < 3; dp++) {
            float2 sd2 = __ldg(srow + dp);
#pragma unroll
            for (int e = 0; e < 2; e++) {
                int d = 2 * dp + e;
                float sd = e ? sd2.y : sd2.x;
                u64 sdp = pack2(sd, sd);
                ulonglong2 w = *reinterpret_cast<const ulonglong2*>(g_fc1t + d * HIDDEN + 4 * lane);
                cur01 = fma2(sdp, w.x, cur01);
                cur23 = fma2(sdp, w.y, cur23);
            }
        }
    }

    u64 syn1_01 = 0, syn1_23 = 0, mem1_01 = 0, mem1_23 = 0;
    u64 syn2_01 = 0, syn2_23 = 0, mem2_01 = 0, mem2_23 = 0;
    u64 spk1n_01 = 0, spk1n_23 = 0;   // spike "values" {0,-thr1}
    u64 r1p01 = 0, r1p23 = 0;         // pending rec1 contribution
    // cnt32: byte k = spike count for unit k (bits 0..6) | "spiked last step"
    // flag (bit 7). Counts <= 8 so no overflow into the flag.
    unsigned cnt32 = 0;
    bool live1 = !(thr2 > 0.f);       // force full path if thr2 <= 0 / NaN
    bool live2 = false;               // layer-2 spiked on previous step

#pragma unroll
    for (int t = 0; t < NUM_STEPS; t++) {
        const bool LAST = (t == NUM_STEPS - 1);

        // ---------- layer 1 state ----------
        syn1_01 = fma2(a1p, syn1_01, cur01);
        syn1_23 = fma2(a1p, syn1_23, cur23);
        if (live1) {
            syn1_01 = add2(syn1_01, r1p01);
            syn1_23 = add2(syn1_23, r1p23);
            mem1_01 = fma2(b1p, mem1_01, syn1_01);
            mem1_23 = fma2(b1p, mem1_23, syn1_23);
            mem1_01 = add2(mem1_01, spk1n_01);   // reset-by-subtract ({0,-thr1})
            mem1_23 = add2(mem1_23, spk1n_23);
        } else {
            mem1_01 = fma2(b1p, mem1_01, syn1_01);
            mem1_23 = fma2(b1p, mem1_23, syn1_23);
        }

        float f0, f1, f2, f3;
        unpack2(mem1_01, f0, f1);
        unpack2(mem1_23, f2, f3);
        bool s0 = f0 > thr1, s1 = f1 > thr1, s2 = f2 > thr1, s3 = f3 > thr1;

        bool active;
        if (live1) active = true;
        else       active = __any_sync(0xffffffffu, s0 | s1 | s2 | s3);

        if (active) {
            live1 = true;
            unsigned m1[4];
            m1[0] = __ballot_sync(0xffffffffu, s0);
            m1[1] = __ballot_sync(0xffffffffu, s1);
            m1[2] = __ballot_sync(0xffffffffu, s2);
            m1[3] = __ballot_sync(0xffffffffu, s3);
            if (!LAST) {
                spk1n_01 = pack2(s0 ? nthr1 : 0.f, s1 ? nthr1 : 0.f);
                spk1n_23 = pack2(s2 ? nthr1 : 0.f, s3 ? nthr1 : 0.f);
            }

            // ---------- layer 2 (+ pre-gather next step's rec1 if needed) ----------
            syn2_01 = mul2(a2p, syn2_01);
            syn2_23 = mul2(a2p, syn2_23);
            if (!LAST) {
                r1p01 = 0; r1p23 = 0;
                gather_fused<true>(m1, lane, syn2_01, syn2_23, r1p01, r1p23);
            } else {
                gather_fused<false>(m1, lane, syn2_01, syn2_23, r1p01, r1p23);
            }
            if (live2) {
                // re-ballot the previous step's layer-2 spike mask from the
                // per-thread flag bits stashed in cnt32 (rare path)
                unsigned m2w[4];
                m2w[0] = __ballot_sync(0xffffffffu, (cnt32 >> 7)  & 1u);
                m2w[1] = __ballot_sync(0xffffffffu, (cnt32 >> 15) & 1u);
                m2w[2] = __ballot_sync(0xffffffffu, (cnt32 >> 23) & 1u);
                m2w[3] = __ballot_sync(0xffffffffu, (cnt32 >> 31) & 1u);
                gather2(g_rec2t, m2w, lane, syn2_01, syn2_23);
            }

            mem2_01 = fma2(b2p, mem2_01, syn2_01);
            mem2_23 = fma2(b2p, mem2_23, syn2_23);
            if (live2) {
                // reset values {0,-thr2} from this thread's own flag bits (rare)
                float nthr2 = -thr2;
                float r0 = ((cnt32 >> 7)  & 1u) ? nthr2 : 0.f;
                float r1 = ((cnt32 >> 15) & 1u) ? nthr2 : 0.f;
                float r2 = ((cnt32 >> 23) & 1u) ? nthr2 : 0.f;
                float r3 = ((cnt32 >> 31) & 1u) ? nthr2 : 0.f;
                mem2_01 = add2(mem2_01, pack2(r0, r1));
                mem2_23 = add2(mem2_23, pack2(r2, r3));
            }

            unpack2(mem2_01, f0, f1);
            unpack2(mem2_23, f2, f3);
            bool t0 = f0 > thr2, t1 = f1 > thr2, t2 = f2 > thr2, t3 = f3 > thr2;
            if (__any_sync(0xffffffffu, t0 | t1 | t2 | t3)) {
                unsigned counts = (t0 ? 1u : 0u) | (t1 ? (1u << 8) : 0u)
                                | (t2 ? (1u << 16) : 0u) | (t3 ? (1u << 24) : 0u);
                if (!LAST) {
                    unsigned flags = (t0 ? (1u << 7) : 0u)  | (t1 ? (1u << 15) : 0u)
                                   | (t2 ? (1u << 23) : 0u) | (t3 ? (1u << 31) : 0u);
                    cnt32 = ((cnt32 & 0x7F7F7F7Fu) + counts) | flags;
                    live2 = true;
                } else {
                    cnt32 = (cnt32 & 0x7F7F7F7Fu) + counts;   // flags dead after last step
                }
            } else if (!LAST && live2) {
                cnt32 &= 0x7F7F7F7Fu;   // clear stale flags
                live2 = false;
            }
        }
        // quiet step: spk1n/r1p/syn2/mem2/cnt32 all remain exactly 0.
    }

    // ---- epilogue ----
    // Common case: no layer-2 spike anywhere in this warp -> avg_spikes == 0
    // exactly -> dm = ds = 0 exactly (finite weights) -> constant outputs,
    // computed with the SAME float expressions as the slow path (bit-identical).
    if (!__any_sync(0xffffffffu, cnt32 != 0u)) {
        if (lane == 0) {
            out[b] = 0.0f;                              // tanhf(0) == 0
            float sig = 1.f / (1.f + expf(-2.f));       // sigmoid(0 + 2)
            out[B + b] = (MAX_STD - MIN_STD) * sig + MIN_STD;
        }
        return;
    }

    const float inv = 1.f / (float)NUM_STEPS;
    float c0 = (float)( cnt32        & 0x7Fu) * inv;
    float c1 = (float)((cnt32 >> 8)  & 0x7Fu) * inv;
    float c2 = (float)((cnt32 >> 16) & 0x7Fu) * inv;
    float c3 = (float)((cnt32 >> 24) & 0x7Fu) * inv;

    float4 wm = *reinterpret_cast<const float4*>(w_mean + 4 * lane);
    float4 ws = *reinterpret_cast<const float4*>(w_std  + 4 * lane);
    float dm = fmaf(c0, wm.x, fmaf(c1, wm.y, fmaf(c2, wm.z, c3 * wm.w)));
    float ds = fmaf(c0, ws.x, fmaf(c1, ws.y, fmaf(c2, ws.z, c3 * ws.w)));
#pragma unroll
    for (int off = 16; off > 0; off >>= 1) {
        dm += __shfl_xor_sync(0xffffffffu, dm, off);
        ds += __shfl_xor_sync(0xffffffffu, ds, off);
    }
    if (lane == 0) {
        out[b] = tanhf(dm);
        float sig = 1.f / (1.f + expf(-(ds + 2.f)));
        out[B + b] = (MAX_STD - MIN_STD) * sig + MIN_STD;
    }
}

extern "C" void kernel_launch(void* const* d_in, const int* in_sizes, int n_in,
                              void* d_out, int out_size) {
    const float* state  = (const float*)d_in[0];
    const float* w_fc1  = (const float*)d_in[1];
    const float* w_rec1 = (const float*)d_in[2];
    const float* w_fc2  = (const float*)d_in[3];
    const float* w_rec2 = (const float*)d_in[4];
    const float* w_mean = (const float*)d_in[5];
    const float* w_std  = (const float*)d_in[6];
    const float* a1 = (const float*)d_in[7];
    const float* b1 = (const float*)d_in[8];
    const float* t1 = (const float*)d_in[9];
    const float* a2 = (const float*)d_in[10];
    const float* b2 = (const float*)d_in[11];
    const float* t2 = (const float*)d_in[12];
    float* out = (float*)d_out;

    int B = in_sizes[0] / STATE_DIM;

    snn_transpose_kernel<<<128, 128>>>(w_fc1, w_rec1, w_fc2, w_rec2);

    int total_threads = B * 32;                    // one warp per element
    int blocks = (total_threads + 127) / 128;
    snn_main_kernel<<<blocks, 128>>>(state, w_mean, w_std,
                                     a1, b1, t1, a2, b2, t2, out, B);
}